// round 9
// baseline (speedup 1.0000x reference)
#include <cuda_runtime.h>
#include <cstdint>

// Problem constants
#define Bb   2
#define Nn   2048
#define Dd   1024
#define Hh   16
#define HALFW 64
#define QKV_COLS (3*Dd)   // 3072
#define Mrows (Bb*Nn)     // 4096

// Scratch (device globals; no allocation allowed)
__device__ float g_qkv[(size_t)Mrows*QKV_COLS];
__device__ float g_att[(size_t)Mrows*Dd];
__device__ float g_xr [(size_t)Mrows*Dd];
__device__ float g_Wqkv_r[(size_t)Dd*QKV_COLS];
__device__ float g_Wout_r[(size_t)Dd*Dd];

// ---------------------------------------------------------------------------
__device__ __forceinline__ uint32_t smem_u32(const void* p) {
    uint32_t a;
    asm("{ .reg .u64 t; cvta.to.shared.u64 t, %1; cvt.u32.u64 %0, t; }"
        : "=r"(a) : "l"(p));
    return a;
}
__device__ __forceinline__ float rna_tf32(float x) {
    float r; asm("cvt.rna.tf32.f32 %0, %1;" : "=f"(r) : "f"(x)); return r;
}
#define MMA_TF32(d0,d1,d2,d3, a0,a1,a2,a3, b0,b1) \
    asm volatile( \
        "mma.sync.aligned.m16n8k8.row.col.f32.tf32.tf32.f32 " \
        "{%0,%1,%2,%3}, {%4,%5,%6,%7}, {%8,%9}, {%0,%1,%2,%3};" \
        : "+f"(d0), "+f"(d1), "+f"(d2), "+f"(d3) \
        : "r"(a0), "r"(a1), "r"(a2), "r"(a3), "r"(b0), "r"(b1))

// ---------------------------------------------------------------------------
// tf32 mma.sync GEMM: C[M,N] = A[M,K] @ W[K,N] + bias[N]
// BM=BN=128, BK=32, 3-stage cp.async, 128 threads (4 warps, 2x2 grid of
// 64x64 warp tiles). Crossbar-balanced: 0.125 B/MAC.
// ---------------------------------------------------------------------------
#define BM 128
#define BN 128
#define BK 32
#define STAGES 3
#define ASTR 36    // A row stride (floats): banks 4g+t4, conflict-free
#define BSTR 136   // B k-row stride: banks 8*t4+g, conflict-free
#define STAGE_FLOATS (BM*ASTR + BK*BSTR)   // 4608 + 4352 = 8960
#define GEMM_SMEM (STAGES*STAGE_FLOATS*4)  // 107520 B
#define GTHREADS 128

__device__ __forceinline__ void g_load_stage(uint32_t sbase,
                                             const float* __restrict__ A,
                                             const float* __restrict__ W,
                                             int m0, int n0, int k0,
                                             int N, int K, int tid)
{
    // A tile: 128 rows x 32 k (8 float4 per row)
#pragma unroll
    for (int i = 0; i < 8; i++) {
        int c  = tid + i * GTHREADS;     // 0..1023
        int mm = c >> 3, ch = c & 7;
        uint32_t dst = sbase + (uint32_t)(mm * ASTR + ch * 4) * 4u;
        const float* src = A + (size_t)(m0 + mm) * K + k0 + ch * 4;
        asm volatile("cp.async.cg.shared.global [%0], [%1], 16;" :: "r"(dst), "l"(src));
    }
    // B tile: 32 k-rows x 128 n
    uint32_t bb = sbase + (uint32_t)(BM * ASTR) * 4u;
#pragma unroll
    for (int i = 0; i < 8; i++) {
        int c  = tid + i * GTHREADS;     // 0..1023
        int kr = c >> 5, ch = c & 31;
        uint32_t dst = bb + (uint32_t)(kr * BSTR + ch * 4) * 4u;
        const float* src = W + (size_t)(k0 + kr) * N + n0 + ch * 4;
        asm volatile("cp.async.cg.shared.global [%0], [%1], 16;" :: "r"(dst), "l"(src));
    }
    asm volatile("cp.async.commit_group;" ::: "memory");
}

__global__ __launch_bounds__(GTHREADS, 2)
void tf32_mma_gemm(const float* __restrict__ A, const float* __restrict__ W,
                   const float* __restrict__ bias, float* __restrict__ C,
                   int M, int N, int K)
{
    extern __shared__ float sm[];
    const int tid  = threadIdx.x;
    const int wid  = tid >> 5;
    const int lane = tid & 31;
    const int g    = lane >> 2;
    const int t4   = lane & 3;
    const int m0 = blockIdx.y * BM;
    const int n0 = blockIdx.x * BN;
    const int wm = (wid >> 1) * 64;      // warp M offset
    const int wn = (wid & 1) * 64;       // warp N offset
    const uint32_t smb = smem_u32(sm);

    float acc[4][8][4];
#pragma unroll
    for (int i = 0; i < 4; i++)
#pragma unroll
        for (int j = 0; j < 8; j++)
#pragma unroll
            for (int q = 0; q < 4; q++) acc[i][j][q] = 0.f;

    const int NITER = K / BK;
#pragma unroll
    for (int s = 0; s < STAGES - 1; s++)
        g_load_stage(smb + (uint32_t)(s * STAGE_FLOATS) * 4u, A, W, m0, n0, s * BK, N, K, tid);

    for (int it = 0; it < NITER; it++) {
        asm volatile("cp.async.wait_group %0;" :: "n"(STAGES - 2) : "memory");
        __syncthreads();

        if (it + STAGES - 1 < NITER) {
            int ps = (it + STAGES - 1) % STAGES;
            g_load_stage(smb + (uint32_t)(ps * STAGE_FLOATS) * 4u, A, W,
                         m0, n0, (it + STAGES - 1) * BK, N, K, tid);
        }

        const float* As = sm + (it % STAGES) * STAGE_FLOATS;
        const float* Bs = As + BM * ASTR;
        const uint32_t* Au = (const uint32_t*)As;
        const uint32_t* Bu = (const uint32_t*)Bs;

#pragma unroll
        for (int kk = 0; kk < BK; kk += 8) {
            uint32_t a[4][4];
#pragma unroll
            for (int mt = 0; mt < 4; mt++) {
                int r = wm + mt * 16 + g;
                a[mt][0] = Au[r * ASTR + kk + t4];
                a[mt][1] = Au[(r + 8) * ASTR + kk + t4];
                a[mt][2] = Au[r * ASTR + kk + t4 + 4];
                a[mt][3] = Au[(r + 8) * ASTR + kk + t4 + 4];
            }
#pragma unroll
            for (int nt = 0; nt < 8; nt++) {
                int cn = wn + nt * 8 + g;
                uint32_t b0 = Bu[(kk + t4) * BSTR + cn];
                uint32_t b1 = Bu[(kk + t4 + 4) * BSTR + cn];
#pragma unroll
                for (int mt = 0; mt < 4; mt++)
                    MMA_TF32(acc[mt][nt][0], acc[mt][nt][1], acc[mt][nt][2], acc[mt][nt][3],
                             a[mt][0], a[mt][1], a[mt][2], a[mt][3], b0, b1);
            }
        }
    }

    // Epilogue: direct float2 stores with bias
#pragma unroll
    for (int nt = 0; nt < 8; nt++) {
        int cc = n0 + wn + nt * 8 + 2 * t4;
        float2 bv = *(const float2*)(bias + cc);
#pragma unroll
        for (int mt = 0; mt < 4; mt++) {
            int r0 = m0 + wm + mt * 16 + g;
            float2 o0, o1;
            o0.x = acc[mt][nt][0] + bv.x;  o0.y = acc[mt][nt][1] + bv.y;
            o1.x = acc[mt][nt][2] + bv.x;  o1.y = acc[mt][nt][3] + bv.y;
            *(float2*)(C + (size_t)r0 * N + cc)       = o0;
            *(float2*)(C + (size_t)(r0 + 8) * N + cc) = o1;
        }
    }
}

// ---------------------------------------------------------------------------
// Pre-pass: tf32 rounding (rna)
// ---------------------------------------------------------------------------
__global__ void round_tf32_kernel(const float* __restrict__ in, float* __restrict__ out, int n4)
{
    int i = blockIdx.x * blockDim.x + threadIdx.x;
    if (i < n4) {
        float4 v = ((const float4*)in)[i];
        v.x = rna_tf32(v.x); v.y = rna_tf32(v.y);
        v.z = rna_tf32(v.z); v.w = rna_tf32(v.w);
        ((float4*)out)[i] = v;
    }
}

// ---------------------------------------------------------------------------
// Tensor-core local attention (unchanged from round 7; known-good).
// ---------------------------------------------------------------------------
#define QSTR 68
#define KTSTR 200
#define VSTR 72
#define SSTR 196
#define QS_OFF 0
#define KT_OFF (64*QSTR)
#define VS_OFF (KT_OFF + 64*KTSTR)
#define SC_OFF (VS_OFF + 192*VSTR)
#define ATT_FLOATS (SC_OFF + 64*SSTR)
#define ATT_SMEM (ATT_FLOATS*4)

__global__ __launch_bounds__(256, 1)
void local_attn_mma(const float* __restrict__ qkv, float* __restrict__ out)
{
    extern __shared__ float sm[];
    float* Qs = sm + QS_OFF;
    float* Kt = sm + KT_OFF;
    float* Vs = sm + VS_OFF;
    float* Sc = sm + SC_OFF;

    const int tid  = threadIdx.x;
    const int wid  = tid >> 5;
    const int lane = tid & 31;
    const int g    = lane >> 2;
    const int t4   = lane & 3;
    const int bh = blockIdx.y;
    const int b  = bh / Hh;
    const int h  = bh % Hh;
    const int q0 = blockIdx.x * 64;
    const int k0 = q0 - HALFW;
    const float* base = qkv + (size_t)b * Nn * QKV_COLS + h * 64;

#pragma unroll
    for (int r = 0; r < 4; r++) {
        int f   = tid + r * 256;
        int row = f >> 4;
        int c4  = (f & 15) * 4;
        float4 v = *(const float4*)(base + (size_t)(q0 + row) * QKV_COLS + c4);
        v.x = rna_tf32(v.x); v.y = rna_tf32(v.y);
        v.z = rna_tf32(v.z); v.w = rna_tf32(v.w);
        *(float4*)(Qs + row * QSTR + c4) = v;
    }
#pragma unroll
    for (int i = 0; i < 24; i++) {
        int j = wid + i * 8;
        int t = k0 + j;
        float ka = 0.f, kb = 0.f, va = 0.f, vb = 0.f;
        if (t >= 0 && t < Nn) {
            const float* rp = base + (size_t)t * QKV_COLS;
            ka = rna_tf32(rp[Dd + lane]);
            kb = rna_tf32(rp[Dd + 32 + lane]);
            va = rna_tf32(rp[2 * Dd + lane]);
            vb = rna_tf32(rp[2 * Dd + 32 + lane]);
        }
        Kt[lane * KTSTR + j]        = ka;
        Kt[(lane + 32) * KTSTR + j] = kb;
        Vs[j * VSTR + lane]         = va;
        Vs[j * VSTR + 32 + lane]    = vb;
    }
    __syncthreads();

    {
        const int wm = (wid >> 2) * 32;
        const int wn = (wid & 3) * 48;
        const uint32_t* Qu = (const uint32_t*)Qs;
        const uint32_t* Ku = (const uint32_t*)Kt;
        float s[2][6][4];
#pragma unroll
        for (int i = 0; i < 2; i++)
#pragma unroll
            for (int j = 0; j < 6; j++)
#pragma unroll
                for (int q = 0; q < 4; q++) s[i][j][q] = 0.f;

#pragma unroll
        for (int kk = 0; kk < 64; kk += 8) {
            uint32_t a[2][4], bfr[6][2];
#pragma unroll
            for (int mt = 0; mt < 2; mt++) {
                int r = wm + mt * 16 + g;
                a[mt][0] = Qu[r * QSTR + kk + t4];
                a[mt][1] = Qu[(r + 8) * QSTR + kk + t4];
                a[mt][2] = Qu[r * QSTR + kk + t4 + 4];
                a[mt][3] = Qu[(r + 8) * QSTR + kk + t4 + 4];
            }
#pragma unroll
            for (int nt = 0; nt < 6; nt++) {
                int cn = wn + nt * 8 + g;
                bfr[nt][0] = Ku[(kk + t4) * KTSTR + cn];
                bfr[nt][1] = Ku[(kk + t4 + 4) * KTSTR + cn];
            }
#pragma unroll
            for (int mt = 0; mt < 2; mt++)
#pragma unroll
                for (int nt = 0; nt < 6; nt++)
                    MMA_TF32(s[mt][nt][0], s[mt][nt][1], s[mt][nt][2], s[mt][nt][3],
                             a[mt][0], a[mt][1], a[mt][2], a[mt][3],
                             bfr[nt][0], bfr[nt][1]);
        }

        const float scale = 0.125f;
#pragma unroll
        for (int mt = 0; mt < 2; mt++) {
#pragma unroll
            for (int nt = 0; nt < 6; nt++) {
                int col = wn + nt * 8 + 2 * t4;
#pragma unroll
                for (int half = 0; half < 2; half++) {
                    int qi = wm + mt * 16 + g + half * 8;
                    float v0 = s[mt][nt][2 * half + 0];
                    float v1 = s[mt][nt][2 * half + 1];
                    int j0 = col, j1 = col + 1;
                    bool ok0 = (j0 >= qi) && (j0 <= qi + 2 * HALFW) &&
                               (k0 + j0 >= 0) && (k0 + j0 < Nn);
                    bool ok1 = (j1 >= qi) && (j1 <= qi + 2 * HALFW) &&
                               (k0 + j1 >= 0) && (k0 + j1 < Nn);
                    float2 o;
                    o.x = ok0 ? v0 * scale : -1e30f;
                    o.y = ok1 ? v1 * scale : -1e30f;
                    *(float2*)(Sc + qi * SSTR + col) = o;
                }
            }
        }
    }
    __syncthreads();

    for (int r = wid; r < 64; r += 8) {
        float m = -1e30f;
        for (int j = lane; j < 192; j += 32) m = fmaxf(m, Sc[r * SSTR + j]);
#pragma unroll
        for (int o = 16; o > 0; o >>= 1) m = fmaxf(m, __shfl_xor_sync(0xffffffffu, m, o));
        float ssum = 0.f;
        for (int j = lane; j < 192; j += 32) {
            float e = __expf(Sc[r * SSTR + j] - m);
            Sc[r * SSTR + j] = e;
            ssum += e;
        }
#pragma unroll
        for (int o = 16; o > 0; o >>= 1) ssum += __shfl_xor_sync(0xffffffffu, ssum, o);
        float inv = 1.f / ssum;
        for (int j = lane; j < 192; j += 32)
            Sc[r * SSTR + j] = rna_tf32(Sc[r * SSTR + j] * inv);
    }
    __syncthreads();

    {
        const int wm = (wid >> 1) * 16;
        const int wn = (wid & 1) * 32;
        const uint32_t* Pu = (const uint32_t*)Sc;
        const uint32_t* Vu = (const uint32_t*)Vs;
        float o[4][4];
#pragma unroll
        for (int i = 0; i < 4; i++)
#pragma unroll
            for (int q = 0; q < 4; q++) o[i][q] = 0.f;

#pragma unroll 4
        for (int kk = 0; kk < 192; kk += 8) {
            uint32_t a[4], bfr[4][2];
            int r = wm + g;
            a[0] = Pu[r * SSTR + kk + t4];
            a[1] = Pu[(r + 8) * SSTR + kk + t4];
            a[2] = Pu[r * SSTR + kk + t4 + 4];
            a[3] = Pu[(r + 8) * SSTR + kk + t4 + 4];
#pragma unroll
            for (int nt = 0; nt < 4; nt++) {
                int cn = wn + nt * 8 + g;
                bfr[nt][0] = Vu[(kk + t4) * VSTR + cn];
                bfr[nt][1] = Vu[(kk + t4 + 4) * VSTR + cn];
            }
#pragma unroll
            for (int nt = 0; nt < 4; nt++)
                MMA_TF32(o[nt][0], o[nt][1], o[nt][2], o[nt][3],
                         a[0], a[1], a[2], a[3], bfr[nt][0], bfr[nt][1]);
        }

#pragma unroll
        for (int nt = 0; nt < 4; nt++) {
            int d = wn + nt * 8 + 2 * t4;
#pragma unroll
            for (int half = 0; half < 2; half++) {
                int qi = wm + g + half * 8;
                float2 ov;
                ov.x = rna_tf32(o[nt][2 * half + 0]);
                ov.y = rna_tf32(o[nt][2 * half + 1]);
                *(float2*)(out + (size_t)(b * Nn + q0 + qi) * Dd + h * 64 + d) = ov;
            }
        }
    }
}

// ---------------------------------------------------------------------------
extern "C" void kernel_launch(void* const* d_in, const int* in_sizes, int n_in,
                              void* d_out, int out_size)
{
    const float* x    = (const float*)d_in[0];
    const float* Wqkv = (const float*)d_in[1];
    const float* bqkv = (const float*)d_in[2];
    const float* Wout = (const float*)d_in[3];
    const float* bout = (const float*)d_in[4];
    float* out = (float*)d_out;

    float *qkv, *att, *xr, *Wr1, *Wr2;
    cudaGetSymbolAddress((void**)&qkv, g_qkv);
    cudaGetSymbolAddress((void**)&att, g_att);
    cudaGetSymbolAddress((void**)&xr,  g_xr);
    cudaGetSymbolAddress((void**)&Wr1, g_Wqkv_r);
    cudaGetSymbolAddress((void**)&Wr2, g_Wout_r);

    // Pre-passes: tf32 rounding
    {
        int n4;
        n4 = Mrows * Dd / 4;
        round_tf32_kernel<<<(n4 + 255) / 256, 256>>>(x, xr, n4);
        n4 = Dd * QKV_COLS / 4;
        round_tf32_kernel<<<(n4 + 255) / 256, 256>>>(Wqkv, Wr1, n4);
        n4 = Dd * Dd / 4;
        round_tf32_kernel<<<(n4 + 255) / 256, 256>>>(Wout, Wr2, n4);
    }

    // 1) QKV projection (tensor tf32)
    {
        cudaFuncSetAttribute(tf32_mma_gemm,
                             cudaFuncAttributeMaxDynamicSharedMemorySize, GEMM_SMEM);
        dim3 grid(QKV_COLS / BN, Mrows / BM);
        tf32_mma_gemm<<<grid, GTHREADS, GEMM_SMEM>>>(xr, Wr1, bqkv, qkv, Mrows, QKV_COLS, Dd);
    }

    // 2) Banded local attention (tensor tf32)
    {
        cudaFuncSetAttribute(local_attn_mma,
                             cudaFuncAttributeMaxDynamicSharedMemorySize, ATT_SMEM);
        dim3 grid(Nn / 64, Bb * Hh);
        local_attn_mma<<<grid, 256, ATT_SMEM>>>(qkv, att);
    }

    // 3) Output projection (tensor tf32)
    {
        dim3 grid(Dd / BN, Mrows / BM);
        tf32_mma_gemm<<<grid, GTHREADS, GEMM_SMEM>>>(att, Wr2, bout, out, Mrows, Dd, Dd);
    }
}

// round 10
// speedup vs baseline: 1.2022x; 1.2022x over previous
#include <cuda_runtime.h>
#include <cstdint>

// Problem constants
#define Bb   2
#define Nn   2048
#define Dd   1024
#define Hh   16
#define HALFW 64
#define QKV_COLS (3*Dd)   // 3072
#define Mrows (Bb*Nn)     // 4096

// Scratch (device globals; no allocation allowed)
__device__ float g_qkv[(size_t)Mrows*QKV_COLS];
__device__ float g_att[(size_t)Mrows*Dd];
__device__ float g_xr [(size_t)Mrows*Dd];
__device__ float g_Wqkv_r[(size_t)Dd*QKV_COLS];
__device__ float g_Wout_r[(size_t)Dd*Dd];

// ---------------------------------------------------------------------------
__device__ __forceinline__ uint32_t smem_u32(const void* p) {
    uint32_t a;
    asm("{ .reg .u64 t; cvta.to.shared.u64 t, %1; cvt.u32.u64 %0, t; }"
        : "=r"(a) : "l"(p));
    return a;
}
__device__ __forceinline__ float rna_tf32(float x) {
    float r; asm("cvt.rna.tf32.f32 %0, %1;" : "=f"(r) : "f"(x)); return r;
}
#define MMA_TF32(d0,d1,d2,d3, a0,a1,a2,a3, b0,b1) \
    asm volatile( \
        "mma.sync.aligned.m16n8k8.row.col.f32.tf32.tf32.f32 " \
        "{%0,%1,%2,%3}, {%4,%5,%6,%7}, {%8,%9}, {%0,%1,%2,%3};" \
        : "+f"(d0), "+f"(d1), "+f"(d2), "+f"(d3) \
        : "r"(a0), "r"(a1), "r"(a2), "r"(a3), "r"(b0), "r"(b1))

// ---------------------------------------------------------------------------
// tf32 mma.sync GEMM (round-9 config; epilogue rna optional via template)
// ---------------------------------------------------------------------------
#define BM 128
#define BN 128
#define BK 32
#define STAGES 3
#define ASTR 36
#define BSTR 136
#define STAGE_FLOATS (BM*ASTR + BK*BSTR)
#define GEMM_SMEM (STAGES*STAGE_FLOATS*4)
#define GTHREADS 128

__device__ __forceinline__ void g_load_stage(uint32_t sbase,
                                             const float* __restrict__ A,
                                             const float* __restrict__ W,
                                             int m0, int n0, int k0,
                                             int N, int K, int tid)
{
#pragma unroll
    for (int i = 0; i < 8; i++) {
        int c  = tid + i * GTHREADS;
        int mm = c >> 3, ch = c & 7;
        uint32_t dst = sbase + (uint32_t)(mm * ASTR + ch * 4) * 4u;
        const float* src = A + (size_t)(m0 + mm) * K + k0 + ch * 4;
        asm volatile("cp.async.cg.shared.global [%0], [%1], 16;" :: "r"(dst), "l"(src));
    }
    uint32_t bb = sbase + (uint32_t)(BM * ASTR) * 4u;
#pragma unroll
    for (int i = 0; i < 8; i++) {
        int c  = tid + i * GTHREADS;
        int kr = c >> 5, ch = c & 31;
        uint32_t dst = bb + (uint32_t)(kr * BSTR + ch * 4) * 4u;
        const float* src = W + (size_t)(k0 + kr) * N + n0 + ch * 4;
        asm volatile("cp.async.cg.shared.global [%0], [%1], 16;" :: "r"(dst), "l"(src));
    }
    asm volatile("cp.async.commit_group;" ::: "memory");
}

template<bool RNA>
__global__ __launch_bounds__(GTHREADS, 2)
void tf32_mma_gemm(const float* __restrict__ A, const float* __restrict__ W,
                   const float* __restrict__ bias, float* __restrict__ C,
                   int M, int N, int K)
{
    extern __shared__ float sm[];
    const int tid  = threadIdx.x;
    const int wid  = tid >> 5;
    const int lane = tid & 31;
    const int g    = lane >> 2;
    const int t4   = lane & 3;
    const int m0 = blockIdx.y * BM;
    const int n0 = blockIdx.x * BN;
    const int wm = (wid >> 1) * 64;
    const int wn = (wid & 1) * 64;
    const uint32_t smb = smem_u32(sm);

    float acc[4][8][4];
#pragma unroll
    for (int i = 0; i < 4; i++)
#pragma unroll
        for (int j = 0; j < 8; j++)
#pragma unroll
            for (int q = 0; q < 4; q++) acc[i][j][q] = 0.f;

    const int NITER = K / BK;
#pragma unroll
    for (int s = 0; s < STAGES - 1; s++)
        g_load_stage(smb + (uint32_t)(s * STAGE_FLOATS) * 4u, A, W, m0, n0, s * BK, N, K, tid);

    for (int it = 0; it < NITER; it++) {
        asm volatile("cp.async.wait_group %0;" :: "n"(STAGES - 2) : "memory");
        __syncthreads();

        if (it + STAGES - 1 < NITER) {
            int ps = (it + STAGES - 1) % STAGES;
            g_load_stage(smb + (uint32_t)(ps * STAGE_FLOATS) * 4u, A, W,
                         m0, n0, (it + STAGES - 1) * BK, N, K, tid);
        }

        const float* As = sm + (it % STAGES) * STAGE_FLOATS;
        const float* Bs = As + BM * ASTR;
        const uint32_t* Au = (const uint32_t*)As;
        const uint32_t* Bu = (const uint32_t*)Bs;

#pragma unroll
        for (int kk = 0; kk < BK; kk += 8) {
            uint32_t a[4][4];
#pragma unroll
            for (int mt = 0; mt < 4; mt++) {
                int r = wm + mt * 16 + g;
                a[mt][0] = Au[r * ASTR + kk + t4];
                a[mt][1] = Au[(r + 8) * ASTR + kk + t4];
                a[mt][2] = Au[r * ASTR + kk + t4 + 4];
                a[mt][3] = Au[(r + 8) * ASTR + kk + t4 + 4];
            }
#pragma unroll
            for (int nt = 0; nt < 8; nt++) {
                int cn = wn + nt * 8 + g;
                uint32_t b0 = Bu[(kk + t4) * BSTR + cn];
                uint32_t b1 = Bu[(kk + t4 + 4) * BSTR + cn];
#pragma unroll
                for (int mt = 0; mt < 4; mt++)
                    MMA_TF32(acc[mt][nt][0], acc[mt][nt][1], acc[mt][nt][2], acc[mt][nt][3],
                             a[mt][0], a[mt][1], a[mt][2], a[mt][3], b0, b1);
            }
        }
    }

#pragma unroll
    for (int nt = 0; nt < 8; nt++) {
        int cc = n0 + wn + nt * 8 + 2 * t4;
        float2 bv = *(const float2*)(bias + cc);
#pragma unroll
        for (int mt = 0; mt < 4; mt++) {
            int r0 = m0 + wm + mt * 16 + g;
            float2 o0, o1;
            o0.x = acc[mt][nt][0] + bv.x;  o0.y = acc[mt][nt][1] + bv.y;
            o1.x = acc[mt][nt][2] + bv.x;  o1.y = acc[mt][nt][3] + bv.y;
            if (RNA) {
                o0.x = rna_tf32(o0.x); o0.y = rna_tf32(o0.y);
                o1.x = rna_tf32(o1.x); o1.y = rna_tf32(o1.y);
            }
            *(float2*)(C + (size_t)r0 * N + cc)       = o0;
            *(float2*)(C + (size_t)(r0 + 8) * N + cc) = o1;
        }
    }
}

// ---------------------------------------------------------------------------
// Pre-pass: tf32 rounding (rna)
// ---------------------------------------------------------------------------
__global__ void round_tf32_kernel(const float* __restrict__ in, float* __restrict__ out, int n4)
{
    int i = blockIdx.x * blockDim.x + threadIdx.x;
    if (i < n4) {
        float4 v = ((const float4*)in)[i];
        v.x = rna_tf32(v.x); v.y = rna_tf32(v.y);
        v.z = rna_tf32(v.z); v.w = rna_tf32(v.w);
        ((float4*)out)[i] = v;
    }
}

// ---------------------------------------------------------------------------
// Tensor-core local attention, v2.
// qkv is already tf32-rounded (QKV GEMM epilogue) -> raw cp.async loads.
// Scores computed transposed: St[j][qi] = K·Q^T (K,V row-major; only Q transposed).
// Softmax column-wise on St (stride 65 => conflict-free), P overlays Ks.
// Grid (N/64, B*H), 256 threads.
// ---------------------------------------------------------------------------
#define QT_STR 72   // Qt[d][qi], B-operand: stride ≡ 8 (mod 32)
#define KS_STR 68   // Ks[j][d],  A-operand: stride ≡ 4 (mod 32)
#define VS_STR 72   // Vs[j][d],  B-operand: ≡ 8
#define ST_STR 65   // St[j][qi]: ≡ 1 -> conflict-free column access
#define P_STR  196  // P[qi][j],  A-operand: ≡ 4
#define QT_OFF 0
#define KS_OFF (64*QT_STR)             // 4608
#define VS_OFF (KS_OFF + 192*KS_STR)   // 17664
#define ST_OFF (VS_OFF + 192*VS_STR)   // 31488
#define P_OFF  KS_OFF                  // P (64*196=12544) overlays Ks (13056)
#define ATT_FLOATS (ST_OFF + 192*ST_STR)  // 43968
#define ATT_SMEM (ATT_FLOATS*4)           // 175872 B

__global__ __launch_bounds__(256, 1)
void local_attn_mma(const float* __restrict__ qkv, float* __restrict__ out)
{
    extern __shared__ float sm[];
    float* Qt = sm + QT_OFF;
    float* Ks = sm + KS_OFF;
    float* Vs = sm + VS_OFF;
    float* St = sm + ST_OFF;
    float* Pp = sm + P_OFF;

    const int tid  = threadIdx.x;
    const int wid  = tid >> 5;
    const int lane = tid & 31;
    const int g    = lane >> 2;
    const int t4   = lane & 3;
    const int bh = blockIdx.y;
    const int b  = bh / Hh;
    const int h  = bh % Hh;
    const int q0 = blockIdx.x * 64;
    const int k0 = q0 - HALFW;
    const float* base = qkv + (size_t)b * Nn * QKV_COLS + h * 64;
    const uint32_t smb = smem_u32(sm);

    // --- K,V via cp.async (zero-fill OOB rows) ---
#pragma unroll
    for (int i = 0; i < 12; i++) {
        int c   = tid + i * 256;        // 0..3071
        int row = c >> 4;
        int ch  = c & 15;
        int t   = k0 + row;
        int tc  = t < 0 ? 0 : (t >= Nn ? Nn - 1 : t);
        int sz  = (t >= 0 && t < Nn) ? 16 : 0;
        const float* srck = base + (size_t)tc * QKV_COLS + Dd + ch * 4;
        const float* srcv = srck + Dd;
        uint32_t dk = smb + (uint32_t)(KS_OFF + row * KS_STR) * 4u + ch * 16;
        uint32_t dv = smb + (uint32_t)(VS_OFF + row * VS_STR) * 4u + ch * 16;
        asm volatile("cp.async.cg.shared.global [%0], [%1], 16, %2;"
                     :: "r"(dk), "l"(srck), "r"(sz));
        asm volatile("cp.async.cg.shared.global [%0], [%1], 16, %2;"
                     :: "r"(dv), "l"(srcv), "r"(sz));
    }
    asm volatile("cp.async.commit_group;" ::: "memory");

    // --- Q transpose (scalar; overlaps with cp.async) ---
#pragma unroll
    for (int i = 0; i < 8; i++) {
        int qi = wid + i * 8;           // 0..63
        const float* rp = base + (size_t)(q0 + qi) * QKV_COLS;
        float v0 = rp[lane];
        float v1 = rp[lane + 32];
        Qt[lane * QT_STR + qi]        = v0;
        Qt[(lane + 32) * QT_STR + qi] = v1;
    }
    asm volatile("cp.async.wait_group 0;" ::: "memory");
    __syncthreads();

    // --- scores (transposed): St[j][qi] = K·Q^T ; warp grid 4(j) x 2(qi) ---
    {
        const int wmJ = (wid >> 1) * 48;
        const int wnQ = (wid & 1) * 32;
        const uint32_t* Ku = (const uint32_t*)Ks;
        const uint32_t* Qu = (const uint32_t*)Qt;
        float s[3][4][4];
#pragma unroll
        for (int i = 0; i < 3; i++)
#pragma unroll
            for (int j = 0; j < 4; j++)
#pragma unroll
                for (int q = 0; q < 4; q++) s[i][j][q] = 0.f;

#pragma unroll
        for (int kk = 0; kk < 64; kk += 8) {
            uint32_t a[3][4], bfr[4][2];
#pragma unroll
            for (int mt = 0; mt < 3; mt++) {
                int r = wmJ + mt * 16 + g;
                a[mt][0] = Ku[r * KS_STR + kk + t4];
                a[mt][1] = Ku[(r + 8) * KS_STR + kk + t4];
                a[mt][2] = Ku[r * KS_STR + kk + t4 + 4];
                a[mt][3] = Ku[(r + 8) * KS_STR + kk + t4 + 4];
            }
#pragma unroll
            for (int nt = 0; nt < 4; nt++) {
                int cn = wnQ + nt * 8 + g;
                bfr[nt][0] = Qu[(kk + t4) * QT_STR + cn];
                bfr[nt][1] = Qu[(kk + t4 + 4) * QT_STR + cn];
            }
#pragma unroll
            for (int mt = 0; mt < 3; mt++)
#pragma unroll
                for (int nt = 0; nt < 4; nt++)
                    MMA_TF32(s[mt][nt][0], s[mt][nt][1], s[mt][nt][2], s[mt][nt][3],
                             a[mt][0], a[mt][1], a[mt][2], a[mt][3],
                             bfr[nt][0], bfr[nt][1]);
        }

        // mask + scale, scalar stores into St[j][qi]
        const float scale = 0.125f;
#pragma unroll
        for (int mt = 0; mt < 3; mt++) {
#pragma unroll
            for (int nt = 0; nt < 4; nt++) {
                int qi0 = wnQ + nt * 8 + 2 * t4;
#pragma unroll
                for (int half = 0; half < 2; half++) {
                    int j = wmJ + mt * 16 + g + half * 8;
                    int t = k0 + j;
                    bool tin = (t >= 0) && (t < Nn);
                    float v0 = s[mt][nt][2 * half + 0];
                    float v1 = s[mt][nt][2 * half + 1];
                    bool ok0 = (j >= qi0) && (j <= qi0 + 2 * HALFW) && tin;
                    bool ok1 = (j >= qi0 + 1) && (j <= qi0 + 1 + 2 * HALFW) && tin;
                    St[j * ST_STR + qi0]     = ok0 ? v0 * scale : -1e30f;
                    St[j * ST_STR + qi0 + 1] = ok1 ? v1 * scale : -1e30f;
                }
            }
        }
    }
    __syncthreads();

    // --- softmax per qi (column of St), 8 columns/warp, single read pass ---
#pragma unroll
    for (int i = 0; i < 8; i++) {
        int qi = wid * 8 + i;
        float v[6];
#pragma unroll
        for (int jj = 0; jj < 6; jj++)
            v[jj] = St[(lane + 32 * jj) * ST_STR + qi];
        float m = v[0];
#pragma unroll
        for (int jj = 1; jj < 6; jj++) m = fmaxf(m, v[jj]);
#pragma unroll
        for (int o = 16; o > 0; o >>= 1) m = fmaxf(m, __shfl_xor_sync(0xffffffffu, m, o));
        float e[6], ssum = 0.f;
#pragma unroll
        for (int jj = 0; jj < 6; jj++) { e[jj] = __expf(v[jj] - m); ssum += e[jj]; }
#pragma unroll
        for (int o = 16; o > 0; o >>= 1) ssum += __shfl_xor_sync(0xffffffffu, ssum, o);
        float inv = 1.f / ssum;
#pragma unroll
        for (int jj = 0; jj < 6; jj++)
            Pp[qi * P_STR + lane + 32 * jj] = rna_tf32(e[jj] * inv);
    }
    __syncthreads();

    // --- PV: O[qi][d] = P·V ; warp grid 4(qi) x 2(d) ---
    {
        const int wm = (wid >> 1) * 16;
        const int wn = (wid & 1) * 32;
        const uint32_t* Pu = (const uint32_t*)Pp;
        const uint32_t* Vu = (const uint32_t*)Vs;
        float o[4][4];
#pragma unroll
        for (int i = 0; i < 4; i++)
#pragma unroll
            for (int q = 0; q < 4; q++) o[i][q] = 0.f;

#pragma unroll 4
        for (int kk = 0; kk < 192; kk += 8) {
            uint32_t a[4], bfr[4][2];
            int r = wm + g;
            a[0] = Pu[r * P_STR + kk + t4];
            a[1] = Pu[(r + 8) * P_STR + kk + t4];
            a[2] = Pu[r * P_STR + kk + t4 + 4];
            a[3] = Pu[(r + 8) * P_STR + kk + t4 + 4];
#pragma unroll
            for (int nt = 0; nt < 4; nt++) {
                int cn = wn + nt * 8 + g;
                bfr[nt][0] = Vu[(kk + t4) * VS_STR + cn];
                bfr[nt][1] = Vu[(kk + t4 + 4) * VS_STR + cn];
            }
#pragma unroll
            for (int nt = 0; nt < 4; nt++)
                MMA_TF32(o[nt][0], o[nt][1], o[nt][2], o[nt][3],
                         a[0], a[1], a[2], a[3], bfr[nt][0], bfr[nt][1]);
        }

#pragma unroll
        for (int nt = 0; nt < 4; nt++) {
            int d = wn + nt * 8 + 2 * t4;
#pragma unroll
            for (int half = 0; half < 2; half++) {
                int qi = wm + g + half * 8;
                float2 ov;
                ov.x = rna_tf32(o[nt][2 * half + 0]);
                ov.y = rna_tf32(o[nt][2 * half + 1]);
                *(float2*)(out + (size_t)(b * Nn + q0 + qi) * Dd + h * 64 + d) = ov;
            }
        }
    }
}

// ---------------------------------------------------------------------------
extern "C" void kernel_launch(void* const* d_in, const int* in_sizes, int n_in,
                              void* d_out, int out_size)
{
    const float* x    = (const float*)d_in[0];
    const float* Wqkv = (const float*)d_in[1];
    const float* bqkv = (const float*)d_in[2];
    const float* Wout = (const float*)d_in[3];
    const float* bout = (const float*)d_in[4];
    float* out = (float*)d_out;

    float *qkv, *att, *xr, *Wr1, *Wr2;
    cudaGetSymbolAddress((void**)&qkv, g_qkv);
    cudaGetSymbolAddress((void**)&att, g_att);
    cudaGetSymbolAddress((void**)&xr,  g_xr);
    cudaGetSymbolAddress((void**)&Wr1, g_Wqkv_r);
    cudaGetSymbolAddress((void**)&Wr2, g_Wout_r);

    // Pre-passes: tf32 rounding
    {
        int n4;
        n4 = Mrows * Dd / 4;
        round_tf32_kernel<<<(n4 + 255) / 256, 256>>>(x, xr, n4);
        n4 = Dd * QKV_COLS / 4;
        round_tf32_kernel<<<(n4 + 255) / 256, 256>>>(Wqkv, Wr1, n4);
        n4 = Dd * Dd / 4;
        round_tf32_kernel<<<(n4 + 255) / 256, 256>>>(Wout, Wr2, n4);
    }

    // 1) QKV projection (tensor tf32), epilogue rna -> qkv pre-rounded
    {
        cudaFuncSetAttribute(tf32_mma_gemm<true>,
                             cudaFuncAttributeMaxDynamicSharedMemorySize, GEMM_SMEM);
        dim3 grid(QKV_COLS / BN, Mrows / BM);
        tf32_mma_gemm<true><<<grid, GTHREADS, GEMM_SMEM>>>(xr, Wr1, bqkv, qkv,
                                                           Mrows, QKV_COLS, Dd);
    }

    // 2) Banded local attention (tensor tf32, cp.async loads)
    {
        cudaFuncSetAttribute(local_attn_mma,
                             cudaFuncAttributeMaxDynamicSharedMemorySize, ATT_SMEM);
        dim3 grid(Nn / 64, Bb * Hh);
        local_attn_mma<<<grid, 256, ATT_SMEM>>>(qkv, att);
    }

    // 3) Output projection (tensor tf32, plain epilogue)
    {
        cudaFuncSetAttribute(tf32_mma_gemm<false>,
                             cudaFuncAttributeMaxDynamicSharedMemorySize, GEMM_SMEM);
        dim3 grid(Dd / BN, Mrows / BM);
        tf32_mma_gemm<false><<<grid, GTHREADS, GEMM_SMEM>>>(att, Wr2, bout, out,
                                                            Mrows, Dd, Dd);
    }
}